// round 10
// baseline (speedup 1.0000x reference)
#include <cuda_runtime.h>

// SSIM fused: separable 11-tap Gaussian conv over 4 planes (x, y, x2+y2, xy),
// packed 2-wide across planes with fma.rn.f32x2 (FFMA2). SSIM epilogue +
// global mean, single kernel, last-block-done reduction.
// N=32, H=W=512 f32, zero-padded "same" conv.

#define NIMG 32
#define IMH  512
#define IMW  512
#define HWSZ (IMH * IMW)

#define TW   32
#define TH   32
#define HALO 5
#define ITH  42              // TH + 2*HALO rows
#define ITW  48              // stored cols: gx0 = tile_x - 8 .. +39 (f4 aligned)
#define HPS  33              // hp row stride in float2 (pad vs 32: bank decorrelation)

#define GRID_X (IMW / TW)    // 16
#define GRID_Y (IMH / TH)    // 16
#define NBLOCKS (GRID_X * GRID_Y * NIMG)  // 8192

#define C1f  1.0e-4f
#define C2f  9.0e-4f
#define EPSf 1.0e-8f

typedef unsigned long long ull;

__device__ __forceinline__ ull pack2(float lo, float hi) {
    ull r; asm("mov.b64 %0,{%1,%2};" : "=l"(r) : "f"(lo), "f"(hi)); return r;
}
__device__ __forceinline__ void unpack2(ull p, float &lo, float &hi) {
    asm("mov.b64 {%0,%1},%2;" : "=f"(lo), "=f"(hi) : "l"(p));
}
// Packed dual fp32 FMA: d.lo = a.lo*b.lo+c.lo ; d.hi = a.hi*b.hi+c.hi
__device__ __forceinline__ ull fma2(ull a, ull b, ull c) {
    ull d; asm("fma.rn.f32x2 %0,%1,%2,%3;" : "=l"(d) : "l"(a), "l"(b), "l"(c)); return d;
}

__device__ float        g_partial[NBLOCKS];
__device__ unsigned int g_count = 0;

__global__ __launch_bounds__(256, 4)
void ssim_tile_kernel(const float* __restrict__ x, const float* __restrict__ y,
                      float* __restrict__ out)
{
    const float G[11] = {
        0.00102838f, 0.00759880f, 0.03600080f, 0.10936040f, 0.21300570f,
        0.26601190f,
        0.21300570f, 0.10936040f, 0.03600080f, 0.00759880f, 0.00102838f
    };

    __shared__ __align__(16) float  sx[ITH * ITW];
    __shared__ __align__(16) float  sy[ITH * ITW];
    __shared__ __align__(16) float2 hpXY[ITH * HPS];   // (hx, hy)
    __shared__ __align__(16) float2 hpSX[ITH * HPS];   // (h(x2+y2), h(xy))
    __shared__ float wred[8];
    __shared__ int   s_last;

    const int tid = threadIdx.x;
    const int img = blockIdx.z;
    const int gx0 = blockIdx.x * TW - 8;
    const int oy  = blockIdx.y * TH - HALO;
    const float* __restrict__ xb = x + img * HWSZ;
    const float* __restrict__ yb = y + img * HWSZ;

    // Broadcast weight pairs (G[k],G[k]); symmetry G[10-k]=G[k] -> 6 pairs.
    ull W2[6];
    #pragma unroll
    for (int k = 0; k < 6; ++k) W2[k] = pack2(G[k], G[k]);

    // ---- Stage 1: gmem -> smem, float4 granularity, whole-f4 predication ----
    for (int i = tid; i < ITH * 12; i += 256) {
        int r  = i / 12;
        int p  = i - r * 12;
        int gy = oy + r;
        int gx = gx0 + 4 * p;
        float4 vx = make_float4(0.f, 0.f, 0.f, 0.f);
        float4 vy = vx;
        if (((unsigned)gy < (unsigned)IMH) && ((unsigned)gx < (unsigned)IMW)) {
            vx = *(const float4*)(xb + gy * IMW + gx);
            vy = *(const float4*)(yb + gy * IMW + gx);
        }
        *(float4*)(sx + r * ITW + 4 * p) = vx;
        *(float4*)(sy + r * ITW + 4 * p) = vy;
    }
    __syncthreads();

    // ---- Stage 2: horizontal conv, 4 outputs/item, packed across planes ----
    // Output col c uses stored j = c+3 .. c+13. Item (r, c0): f[l] = stored[c0+3+l].
    for (int it = tid; it < ITH * 8; it += 256) {
        int r  = it >> 3;
        int c0 = (it & 7) * 4;
        const float* bx_ = sx + r * ITW + c0 + 3;
        const float* by_ = sy + r * ITW + c0 + 3;

        ull aXY[4] = {0ull, 0ull, 0ull, 0ull};   // (ax, ay) per output
        ull aSX[4] = {0ull, 0ull, 0ull, 0ull};   // (ass, axy) per output

        // Process one input lane l: update all valid outputs with packed FMA.
        #define PROC_LANE(L, PX, PY)                                          \
        {   float px_ = (PX), py_ = (PY);                                     \
            ull pxy = pack2(px_, py_);                                        \
            float ss_ = fmaf(py_, py_, px_ * px_);                            \
            ull psx = pack2(ss_, px_ * py_);                                  \
            _Pragma("unroll")                                                 \
            for (int o = 0; o < 4; ++o) {                                     \
                int k = (L) - o;                                              \
                if (k >= 0 && k <= 10) {                                      \
                    ull w = W2[(k <= 5) ? k : 10 - k];                        \
                    aXY[o] = fma2(w, pxy, aXY[o]);                            \
                    aSX[o] = fma2(w, psx, aSX[o]);                            \
                }                                                             \
            }                                                                 \
        }

        PROC_LANE(0, bx_[0], by_[0]);
        #pragma unroll
        for (int q = 0; q < 3; ++q) {
            float4 tx = *(const float4*)(bx_ + 1 + 4 * q);
            float4 ty = *(const float4*)(by_ + 1 + 4 * q);
            PROC_LANE(1 + 4 * q, tx.x, ty.x);
            PROC_LANE(2 + 4 * q, tx.y, ty.y);
            PROC_LANE(3 + 4 * q, tx.z, ty.z);
            PROC_LANE(4 + 4 * q, tx.w, ty.w);
        }
        PROC_LANE(13, bx_[13], by_[13]);
        #undef PROC_LANE

        int hb = r * HPS + c0;
        #pragma unroll
        for (int o = 0; o < 4; ++o) {
            ((ull*)hpXY)[hb + o] = aXY[o];
            ((ull*)hpSX)[hb + o] = aSX[o];
        }
    }
    __syncthreads();

    // ---- Stage 3: vertical conv, 4 rows/thread, packed across planes ----
    const int c  = tid & 31;
    const int r0 = (tid >> 5) * 4;

    ull vXY[4] = {0ull, 0ull, 0ull, 0ull};
    ull vSX[4] = {0ull, 0ull, 0ull, 0ull};

    #pragma unroll
    for (int t = 0; t < 14; ++t) {
        int idx = (r0 + t) * HPS + c;
        ull hxy = ((const ull*)hpXY)[idx];
        ull hsx = ((const ull*)hpSX)[idx];
        #pragma unroll
        for (int r = 0; r < 4; ++r) {
            int k = t - r;
            if (k >= 0 && k <= 10) {
                ull w = W2[(k <= 5) ? k : 10 - k];
                vXY[r] = fma2(w, hxy, vXY[r]);
                vSX[r] = fma2(w, hsx, vSX[r]);
            }
        }
    }

    float lsum = 0.f;
    #pragma unroll
    for (int r = 0; r < 4; ++r) {
        float mu_x, mu_y, ess, exy;
        unpack2(vXY[r], mu_x, mu_y);
        unpack2(vSX[r], ess, exy);
        float m2    = fmaf(mu_x, mu_x, mu_y * mu_y);
        float mu_xy = mu_x * mu_y;
        float sig_ss = ess - m2;
        float sig_xy = exy - mu_xy;
        float num = (2.f * mu_xy + C1f) * (2.f * sig_xy + C2f);
        float den = (m2 + C1f) * (sig_ss + C2f);
        float val = __fdividef(num, den + EPSf);
        val = fminf(fmaxf(val, 0.f), 1.f);
        lsum += val;
    }

    // ---- Block reduction: warp shfl + 8-way smem ----
    #pragma unroll
    for (int s = 16; s > 0; s >>= 1)
        lsum += __shfl_xor_sync(0xffffffffu, lsum, s);
    if ((tid & 31) == 0) wred[tid >> 5] = lsum;
    __syncthreads();

    if (tid == 0) {
        float tot = 0.f;
        #pragma unroll
        for (int w = 0; w < 8; ++w) tot += wred[w];
        int bid = blockIdx.x + GRID_X * (blockIdx.y + GRID_Y * blockIdx.z);
        g_partial[bid] = tot;
        __threadfence();
        unsigned prev = atomicAdd(&g_count, 1u);
        s_last = (prev == (unsigned)(NBLOCKS - 1)) ? 1 : 0;
    }
    __syncthreads();

    // ---- Last block: deterministic final reduction ----
    if (s_last) {
        float s = 0.f;
        for (int i = tid; i < NBLOCKS; i += 256)
            s += g_partial[i];
        #pragma unroll
        for (int k = 16; k > 0; k >>= 1)
            s += __shfl_xor_sync(0xffffffffu, s, k);
        if ((tid & 31) == 0) wred[tid >> 5] = s;
        __syncthreads();
        if (tid == 0) {
            float tot = 0.f;
            #pragma unroll
            for (int w = 0; w < 8; ++w) tot += wred[w];
            out[0] = tot * 0x1p-23f;   // 1/(32*512*512)
            g_count = 0;               // reset for graph replay
        }
    }
}

extern "C" void kernel_launch(void* const* d_in, const int* in_sizes, int n_in,
                              void* d_out, int out_size)
{
    const float* x = (const float*)d_in[0];
    const float* y = (const float*)d_in[1];
    // d_in[2]: Gaussian window — fixed by problem definition, baked in as immediates.
    (void)in_sizes; (void)n_in; (void)out_size;

    dim3 grid(GRID_X, GRID_Y, NIMG);
    ssim_tile_kernel<<<grid, 256>>>(x, y, (float*)d_out);
}

// round 14
// speedup vs baseline: 1.0293x; 1.0293x over previous
#include <cuda_runtime.h>

// SSIM fused: separable 11-tap Gaussian conv (4 planes: x, y, x2+y2, xy).
// Stage2 scalar FFMA-imm (conflict-free), stage3 packed fma.rn.f32x2 on
// interleaved pair planes. SSIM epilogue + global mean, single kernel,
// last-block-done reduction. N=32, H=W=512 f32, zero-padded "same" conv.

#define NIMG 32
#define IMH  512
#define IMW  512
#define HWSZ (IMH * IMW)

#define TW   32
#define TH   32
#define HALO 5
#define ITH  42              // TH + 2*HALO rows
#define ITW  48              // stored cols: gx0 = tile_x - 8 .. +39 (f4 aligned)
#define HPS2 32              // hp row stride in float2 units (even: f4-aligned stores)

#define GRID_X (IMW / TW)    // 16
#define GRID_Y (IMH / TH)    // 16
#define NBLOCKS (GRID_X * GRID_Y * NIMG)  // 8192

#define C1f  1.0e-4f
#define C2f  9.0e-4f
#define EPSf 1.0e-8f

typedef unsigned long long ull;

__device__ __forceinline__ ull pack2(float lo, float hi) {
    ull r; asm("mov.b64 %0,{%1,%2};" : "=l"(r) : "f"(lo), "f"(hi)); return r;
}
__device__ __forceinline__ void unpack2(ull p, float &lo, float &hi) {
    asm("mov.b64 {%0,%1},%2;" : "=f"(lo), "=f"(hi) : "l"(p));
}
// Packed dual fp32 FMA (FFMA2): two independent RN fp32 FMAs per issue slot.
__device__ __forceinline__ ull fma2(ull a, ull b, ull c) {
    ull d; asm("fma.rn.f32x2 %0,%1,%2,%3;" : "=l"(d) : "l"(a), "l"(b), "l"(c)); return d;
}

__device__ float        g_partial[NBLOCKS];
__device__ unsigned int g_count = 0;

__global__ __launch_bounds__(256, 5)
void ssim_tile_kernel(const float* __restrict__ x, const float* __restrict__ y,
                      float* __restrict__ out)
{
    // Compile-time Gaussian weights -> FFMA-imm (rt_SMSP=1) in stage 2.
    const float G[11] = {
        0.00102838f, 0.00759880f, 0.03600080f, 0.10936040f, 0.21300570f,
        0.26601190f,
        0.21300570f, 0.10936040f, 0.03600080f, 0.00759880f, 0.00102838f
    };

    __shared__ __align__(16) float  sx[ITH * ITW];
    __shared__ __align__(16) float  sy[ITH * ITW];
    // Interleaved pair planes: hpXY=(hx,hy), hpSX=(h(x2+y2), h(xy)).
    __shared__ __align__(16) float2 hpXY[ITH * HPS2];
    __shared__ __align__(16) float2 hpSX[ITH * HPS2];
    __shared__ float wred[8];
    __shared__ int   s_last;

    const int tid = threadIdx.x;
    const int img = blockIdx.z;
    const int gx0 = blockIdx.x * TW - 8;   // multiple of 8 -> float4-aligned gmem
    const int oy  = blockIdx.y * TH - HALO;
    const float* __restrict__ xb = x + img * HWSZ;
    const float* __restrict__ yb = y + img * HWSZ;

    // ---- Stage 1: gmem -> smem, float4 granularity, whole-f4 predication ----
    for (int i = tid; i < ITH * 12; i += 256) {
        int r  = i / 12;
        int p  = i - r * 12;
        int gy = oy + r;
        int gx = gx0 + 4 * p;
        float4 vx = make_float4(0.f, 0.f, 0.f, 0.f);
        float4 vy = vx;
        if (((unsigned)gy < (unsigned)IMH) && ((unsigned)gx < (unsigned)IMW)) {
            vx = *(const float4*)(xb + gy * IMW + gx);
            vy = *(const float4*)(yb + gy * IMW + gx);
        }
        *(float4*)(sx + r * ITW + 4 * p) = vx;
        *(float4*)(sy + r * ITW + 4 * p) = vy;
    }
    __syncthreads();

    // ---- Stage 2: horizontal conv, 4 outputs/item, scalar FFMA-imm ----
    // Output col c uses stored j = c+3 .. c+13. Item (r, c0): f[l] = stored[c0+3+l].
    for (int it = tid; it < ITH * 8; it += 256) {
        int r  = it >> 3;
        int c0 = (it & 7) * 4;
        const float* bx_ = sx + r * ITW + c0;
        const float* by_ = sy + r * ITW + c0;

        float fx[14], fy[14];
        fx[0] = bx_[3];  fy[0] = by_[3];
        #pragma unroll
        for (int q = 0; q < 3; ++q) {
            float4 t4 = *(const float4*)(bx_ + 4 + 4 * q);
            fx[1 + 4*q] = t4.x; fx[2 + 4*q] = t4.y; fx[3 + 4*q] = t4.z; fx[4 + 4*q] = t4.w;
            float4 u4 = *(const float4*)(by_ + 4 + 4 * q);
            fy[1 + 4*q] = u4.x; fy[2 + 4*q] = u4.y; fy[3 + 4*q] = u4.z; fy[4 + 4*q] = u4.w;
        }
        fx[13] = bx_[16];  fy[13] = by_[16];

        float ax[4]  = {0.f, 0.f, 0.f, 0.f};
        float ay[4]  = {0.f, 0.f, 0.f, 0.f};
        float ass[4] = {0.f, 0.f, 0.f, 0.f};
        float axy[4] = {0.f, 0.f, 0.f, 0.f};

        #pragma unroll
        for (int l = 0; l < 14; ++l) {
            float px = fx[l], py = fy[l];
            float ss = fmaf(py, py, px * px);   // x^2 + y^2 (linear in conv)
            float xy = px * py;
            #pragma unroll
            for (int o = 0; o < 4; ++o) {
                int k = l - o;
                if (k >= 0 && k < 11) {
                    float w = G[k];             // compile-time immediate
                    ax[o]  = fmaf(w, px, ax[o]);
                    ay[o]  = fmaf(w, py, ay[o]);
                    ass[o] = fmaf(w, ss, ass[o]);
                    axy[o] = fmaf(w, xy, axy[o]);
                }
            }
        }

        // Interleaved pair stores: pure operand ordering, zero packing MOVs.
        int hb = r * HPS2 + c0;   // even -> 16B aligned
        *(float4*)&hpXY[hb]     = make_float4(ax[0], ay[0], ax[1], ay[1]);
        *(float4*)&hpXY[hb + 2] = make_float4(ax[2], ay[2], ax[3], ay[3]);
        *(float4*)&hpSX[hb]     = make_float4(ass[0], axy[0], ass[1], axy[1]);
        *(float4*)&hpSX[hb + 2] = make_float4(ass[2], axy[2], ass[3], axy[3]);
    }
    __syncthreads();

    // ---- Stage 3: vertical conv, packed f32x2 across plane pairs ----
    // Weight pairs built here (post-stage2) to keep peak register pressure low.
    ull W2[6];
    #pragma unroll
    for (int k = 0; k < 6; ++k) W2[k] = pack2(G[k], G[k]);

    const int c  = tid & 31;
    const int r0 = (tid >> 5) * 4;

    ull vXY[4] = {0ull, 0ull, 0ull, 0ull};
    ull vSX[4] = {0ull, 0ull, 0ull, 0ull};

    #pragma unroll
    for (int t = 0; t < 14; ++t) {
        int idx = (r0 + t) * HPS2 + c;
        ull hxy = ((const ull*)hpXY)[idx];   // ld.shared.b64: pair in reg pair
        ull hsx = ((const ull*)hpSX)[idx];
        #pragma unroll
        for (int r = 0; r < 4; ++r) {
            int k = t - r;
            if (k >= 0 && k <= 10) {
                ull w = W2[(k <= 5) ? k : 10 - k];
                vXY[r] = fma2(w, hxy, vXY[r]);
                vSX[r] = fma2(w, hsx, vSX[r]);
            }
        }
    }

    float lsum = 0.f;
    #pragma unroll
    for (int r = 0; r < 4; ++r) {
        float mu_x, mu_y, ess, exy;
        unpack2(vXY[r], mu_x, mu_y);
        unpack2(vSX[r], ess, exy);
        float m2    = fmaf(mu_x, mu_x, mu_y * mu_y);   // mu_x^2 + mu_y^2
        float mu_xy = mu_x * mu_y;
        float sig_ss = ess - m2;                       // sig_x2 + sig_y2
        float sig_xy = exy - mu_xy;
        float num = (2.f * mu_xy + C1f) * (2.f * sig_xy + C2f);
        float den = (m2 + C1f) * (sig_ss + C2f);
        float val = __fdividef(num, den + EPSf);
        val = fminf(fmaxf(val, 0.f), 1.f);
        lsum += val;
    }

    // ---- Block reduction: warp shfl + 8-way smem ----
    #pragma unroll
    for (int s = 16; s > 0; s >>= 1)
        lsum += __shfl_xor_sync(0xffffffffu, lsum, s);
    if ((tid & 31) == 0) wred[tid >> 5] = lsum;
    __syncthreads();

    if (tid == 0) {
        float tot = 0.f;
        #pragma unroll
        for (int w = 0; w < 8; ++w) tot += wred[w];
        int bid = blockIdx.x + GRID_X * (blockIdx.y + GRID_Y * blockIdx.z);
        g_partial[bid] = tot;
        __threadfence();
        unsigned prev = atomicAdd(&g_count, 1u);
        s_last = (prev == (unsigned)(NBLOCKS - 1)) ? 1 : 0;
    }
    __syncthreads();

    // ---- Last block: deterministic final reduction ----
    if (s_last) {
        float s = 0.f;
        for (int i = tid; i < NBLOCKS; i += 256)
            s += g_partial[i];
        #pragma unroll
        for (int k = 16; k > 0; k >>= 1)
            s += __shfl_xor_sync(0xffffffffu, s, k);
        if ((tid & 31) == 0) wred[tid >> 5] = s;
        __syncthreads();
        if (tid == 0) {
            float tot = 0.f;
            #pragma unroll
            for (int w = 0; w < 8; ++w) tot += wred[w];
            out[0] = tot * 0x1p-23f;   // 1/(32*512*512)
            g_count = 0;               // reset for graph replay
        }
    }
}

extern "C" void kernel_launch(void* const* d_in, const int* in_sizes, int n_in,
                              void* d_out, int out_size)
{
    const float* x = (const float*)d_in[0];
    const float* y = (const float*)d_in[1];
    // d_in[2]: Gaussian window — fixed by problem definition, baked in as immediates.
    (void)in_sizes; (void)n_in; (void)out_size;

    dim3 grid(GRID_X, GRID_Y, NIMG);
    ssim_tile_kernel<<<grid, 256>>>(x, y, (float*)d_out);
}